// round 12
// baseline (speedup 1.0000x reference)
#include <cuda_runtime.h>
#include <cuda_bf16.h>
#include <cstdint>

namespace {

constexpr int NCHUNK      = 70;
constexpr int CHUNK_BYTES = 32768;    // [hi 16KB][lo 16KB]; 256 n-rows x 16 words x 4B per plane
constexpr int NTHREADS    = 512;

// SMEM word offsets (uint32 units)
constexpr int W_ACT_H = 0;        // 16384 words (128 rows x 128 words)
constexpr int W_ACT_L = 16384;
constexpr int W_PE_H  = 32768;    // 4096 words (128 rows x 32 words), shared pe_x / pe_d
constexpr int W_PE_L  = 36864;
constexpr int W_WBUF  = 40960;    // 2 x 8192 words
constexpr int SMEM_BYTES = 57344 * 4;   // 229376 <= 232448

__device__ __align__(128) unsigned char WPRE[(size_t)NCHUNK * CHUNK_BYTES];

__constant__ uint8_t CH_L[NCHUNK] = {
    0,0,
    1,1,1,1,1,1,1,1,
    2,2,2,2,2,2,2,2,
    3,3,3,3,3,3,3,3,
    4,4,4,4,4,4,4,4,
    5,5,5,5,5,5,5,5,5,5,
    6,6,6,6,6,6,6,6,
    7,7,7,7,7,7,7,7,
    8,8,8,8,8,8,8,8,8,8};
__constant__ uint16_t CH_K0[NCHUNK] = {
    0,32,
    0,32,64,96,128,160,192,224,
    0,32,64,96,128,160,192,224,
    0,32,64,96,128,160,192,224,
    0,32,64,96,128,160,192,224,
    0,32,64,96,128,160,192,224,256,288,
    0,32,64,96,128,160,192,224,
    0,32,64,96,128,160,192,224,
    0,32,64,96,128,160,192,224,256,288};
__constant__ int8_t NKS[9]    = {4,16,16,16,16,20,16,16,20};
__constant__ int8_t RELU_L[9] = {1,1,1,1,0,1,1,0,1};

// ---------------- helpers ----------------
__device__ __forceinline__ uint32_t smem_u32(const void* p) {
    uint32_t a;
    asm("{ .reg .u64 t; cvta.to.shared.u64 t, %1; cvt.u32.u64 %0, t; }" : "=r"(a) : "l"(p));
    return a;
}
__device__ __forceinline__ void cp_async16(uint32_t s, const void* g) {
    asm volatile("cp.async.cg.shared.global [%0], [%1], 16;" :: "r"(s), "l"(g));
}
__device__ __forceinline__ void cp_commit() { asm volatile("cp.async.commit_group;" ::: "memory"); }
template <int n> __device__ __forceinline__ void cp_wait() {
    asm volatile("cp.async.wait_group %0;" :: "n"(n) : "memory");
}

__device__ __forceinline__ void mma16816(float* c, const uint32_t* a, const uint32_t* b) {
    asm volatile("mma.sync.aligned.m16n8k16.row.col.f32.bf16.bf16.f32 "
        "{%0,%1,%2,%3}, {%4,%5,%6,%7}, {%8,%9}, {%0,%1,%2,%3};"
        : "+f"(c[0]), "+f"(c[1]), "+f"(c[2]), "+f"(c[3])
        : "r"(a[0]), "r"(a[1]), "r"(a[2]), "r"(a[3]), "r"(b[0]), "r"(b[1]));
}

// accurate sin/cos: double range reduction then fp32 sin/cos (matches fp32 ref)
__device__ __forceinline__ void sincos_red(float a, float& s, float& c) {
    double ad = (double)a;
    double k  = rint(ad * 0.15915494309189535);
    float rf  = (float)fma(k, -6.283185307179586, ad);
    s = sinf(rf); c = cosf(rf);
}

struct KPW { const float* W[9]; };
struct KP {
    const float* x; const float* dir;
    const float* b[9];
    const float* sigW; const float* sigb;
    const float* c1W;  const float* c1b;
    float* out;
};

// ---------------- weight prep: split, transpose to [n][k], swizzle, pad ----------------
__global__ void prep_kernel(KPW pw) {
    const int gc = blockIdx.x;
    const int n  = threadIdx.x;
    const int L  = CH_L[gc];
    const int k0 = CH_K0[gc];
    const float* W = pw.W[L];
    unsigned char* dst = WPRE + (size_t)gc * CHUNK_BYTES;
    const int xw = ((n >> 1) & 3) << 2;
#pragma unroll
    for (int kk = 0; kk < 32; ++kk) {
        int r = k0 + kk;
        int rr;
        if (L == 0)      rr = (r < 63) ? r : -1;
        else if (L == 5) rr = (r < 63) ? r : ((r == 63) ? -1 : r - 1);
        else if (L == 8) rr = (r < 39) ? r : ((r < 64) ? -1 : r - 25);
        else             rr = r;
        float v = (rr >= 0) ? W[(size_t)rr * 256 + n] : 0.f;
        __nv_bfloat16 h = __float2bfloat16(v);
        __nv_bfloat16 l = __float2bfloat16(v - __bfloat162float(h));
        int word = (kk >> 1) ^ xw;
        int off  = n * 64 + word * 4 + (kk & 1) * 2;
        *(uint16_t*)(dst + off)         = __bfloat16_as_ushort(h);
        *(uint16_t*)(dst + 16384 + off) = __bfloat16_as_ushort(l);
    }
}

// ---------------- main kernel ----------------
__device__ __forceinline__ void load_chunk(uint32_t dstByte, int c, int tid) {
    const unsigned char* src = WPRE + (size_t)c * CHUNK_BYTES + tid * 16;
    uint32_t d = dstByte + tid * 16;
#pragma unroll
    for (int i = 0; i < 4; ++i)
        cp_async16(d + i * 8192, src + i * 8192);
    cp_commit();
}

__device__ __forceinline__ void put_pe(uint32_t* H, uint32_t* Lp, int m, int kk, float v) {
    __nv_bfloat16 h = __float2bfloat16(v);
    __nv_bfloat16 l = __float2bfloat16(v - __bfloat162float(h));
    int off = m * 32 + ((kk >> 1) ^ ((m & 7) << 2));
    ((uint16_t*)(H  + off))[kk & 1] = __bfloat16_as_ushort(h);
    ((uint16_t*)(Lp + off))[kk & 1] = __bfloat16_as_ushort(l);
}

// build PE planes (128 rows) for src (x: nlev=10, dir: nlev=6). Includes syncs.
__device__ void build_pe(uint32_t* H, uint32_t* Lp, const float* src, int nlev,
                         int base, int tid) {
    for (int i = tid; i < 4096; i += NTHREADS) { H[i] = 0; Lp[i] = 0; }
    __syncthreads();
    if (tid < 384) {
        const int m = tid & 127, comp = tid >> 7;
        const float v = src[(base + m) * 3 + comp];
        put_pe(H, Lp, m, comp, v);
        float f = 1.f;
        for (int l = 0; l < nlev; ++l) {
            float s, c;
            sincos_red(v * f, s, c);
            put_pe(H, Lp, m, 3 + 6 * l + comp, s);
            put_pe(H, Lp, m, 3 + 6 * l + 3 + comp, c);
            f *= 2.f;
        }
    }
    __syncthreads();
}

__global__ __launch_bounds__(NTHREADS, 1) void nerf_mma(KP p) {
    extern __shared__ uint32_t sm4[];
    const int tid  = threadIdx.x;
    const int lane = tid & 31, warp = tid >> 5;
    const int g = lane >> 2, t = lane & 3;
    const int wm = warp & 3, wn = warp >> 2;        // warp grid 4(M) x 4(N), warp tile 32x64
    const int xg = g << 2;                           // A/act swizzle xor
    const int xw = ((g >> 1) & 3) << 2;              // B swizzle xor

    uint32_t* actH = sm4 + W_ACT_H;
    uint32_t* actL = sm4 + W_ACT_L;
    uint32_t* peH  = sm4 + W_PE_H;
    uint32_t* peL  = sm4 + W_PE_L;
    const uint32_t wbufByte = smem_u32(sm4) + W_WBUF * 4;

    // kick off weight prefetch immediately, overlap with PE build
    load_chunk(wbufByte, 0, tid);
    load_chunk(wbufByte + CHUNK_BYTES, 1, tid);

    build_pe(peH, peL, p.x, 10, blockIdx.x * 128, tid);

    float acc[2][8][4];
    float sig = 0.f;
    int gc = 0;

    for (int L = 0; L < 9; ++L) {
        // init accumulators with bias (uniform __ldg, L1-broadcast)
#pragma unroll
        for (int j = 0; j < 8; ++j) {
            const int n0 = wn * 64 + j * 8 + t * 2;
            const float b0 = __ldg(p.b[L] + n0), b1 = __ldg(p.b[L] + n0 + 1);
#pragma unroll
            for (int i2 = 0; i2 < 2; ++i2) {
                acc[i2][j][0] = b0; acc[i2][j][1] = b1;
                acc[i2][j][2] = b0; acc[i2][j][3] = b1;
            }
        }

        const int nck  = NKS[L] >> 1;
        const int koff = (L == 5 || L == 8) ? 4 : 0;
        for (int ck = 0; ck < nck; ++ck) {
            if (gc < NCHUNK - 1) cp_wait<1>(); else cp_wait<0>();
            __syncthreads();
            const uint32_t* Wh  = sm4 + W_WBUF + (gc & 1) * 8192;
            const uint32_t* Wl  = Wh + 4096;
            const uint32_t* Whg = Wh + (wn * 64 + g) * 16;
            const uint32_t* Wlg = Wl + (wn * 64 + g) * 16;

#pragma unroll
            for (int s = 0; s < 2; ++s) {
                const int ks  = ck * 2 + s;
                const int b0i = (s * 8 + t) ^ xw;
                const int b1i = (s * 8 + t + 4) ^ xw;
                uint32_t bh[8][2], bl[8][2];
#pragma unroll
                for (int j = 0; j < 8; ++j) {
                    bh[j][0] = Whg[j * 128 + b0i]; bh[j][1] = Whg[j * 128 + b1i];
                    bl[j][0] = Wlg[j * 128 + b0i]; bl[j][1] = Wlg[j * 128 + b1i];
                }

                const bool pe = (L == 0) || (koff && ks < 4);
                const uint32_t* sH; const uint32_t* sL; int stride, kw;
                if (pe) { sH = peH;  sL = peL;  stride = 32;  kw = ks * 8; }
                else    { sH = actH; sL = actL; stride = 128; kw = (ks - koff) * 8; }
                const int w0s = (kw + t) ^ xg, w1s = (kw + t + 4) ^ xg;

#pragma unroll
                for (int i2 = 0; i2 < 2; ++i2) {
                    const int r0 = wm * 32 + i2 * 16 + g;
                    const uint32_t* hA = sH + r0 * stride;
                    const uint32_t* lA = sL + r0 * stride;
                    uint32_t ah[4], al[4];
                    ah[0] = hA[w0s]; ah[1] = hA[8 * stride + w0s];
                    ah[2] = hA[w1s]; ah[3] = hA[8 * stride + w1s];
                    al[0] = lA[w0s]; al[1] = lA[8 * stride + w0s];
                    al[2] = lA[w1s]; al[3] = lA[8 * stride + w1s];
#pragma unroll
                    for (int j = 0; j < 8; ++j) {
                        mma16816(acc[i2][j], ah, bh[j]);
                        mma16816(acc[i2][j], al, bh[j]);
                        mma16816(acc[i2][j], ah, bl[j]);
                    }
                }
            }
            __syncthreads();
            if (gc + 2 < NCHUNK) load_chunk(wbufByte + (gc & 1) * CHUNK_BYTES, gc + 2, tid);
            ++gc;
        }

        // epilogue: relu, bf16 hi/lo repack, in-place act store
        const bool rl = RELU_L[L];
#pragma unroll
        for (int i2 = 0; i2 < 2; ++i2) {
            const int r0 = wm * 32 + i2 * 16 + g;
#pragma unroll
            for (int j = 0; j < 8; ++j) {
                const int cw  = wn * 32 + j * 4 + t;
                const int sw_ = cw ^ xg;
                float v0 = acc[i2][j][0], v1 = acc[i2][j][1];
                float v2 = acc[i2][j][2], v3 = acc[i2][j][3];
                if (rl) { v0 = fmaxf(v0,0.f); v1 = fmaxf(v1,0.f); v2 = fmaxf(v2,0.f); v3 = fmaxf(v3,0.f); }
                uint32_t h0 = __bfloat16_as_ushort(__float2bfloat16(v0));
                uint32_t h1 = __bfloat16_as_ushort(__float2bfloat16(v1));
                uint32_t h2 = __bfloat16_as_ushort(__float2bfloat16(v2));
                uint32_t h3 = __bfloat16_as_ushort(__float2bfloat16(v3));
                float l0 = v0 - __uint_as_float(h0 << 16);
                float l1 = v1 - __uint_as_float(h1 << 16);
                float l2 = v2 - __uint_as_float(h2 << 16);
                float l3 = v3 - __uint_as_float(h3 << 16);
                actH[r0 * 128 + sw_]       = h0 | (h1 << 16);
                actH[(r0 + 8) * 128 + sw_] = h2 | (h3 << 16);
                actL[r0 * 128 + sw_] =
                    (uint32_t)__bfloat16_as_ushort(__float2bfloat16(l0)) |
                    ((uint32_t)__bfloat16_as_ushort(__float2bfloat16(l1)) << 16);
                actL[(r0 + 8) * 128 + sw_] =
                    (uint32_t)__bfloat16_as_ushort(__float2bfloat16(l2)) |
                    ((uint32_t)__bfloat16_as_ushort(__float2bfloat16(l3)) << 16);
            }
        }
        __syncthreads();

        if (L == 5) {   // pe_x dead; rebuild planes with pe_d for L8
            build_pe(peH, peL, p.dir, 6, blockIdx.x * 128, tid);
        }

        if (L == 7 && tid < 128) {   // sigma head on features2 (raw), kept in register
            const int m = tid, x4 = (m & 7) << 2;
            float s = 0.f;
#pragma unroll 4
            for (int w = 0; w < 128; ++w) {
                const int idx = m * 128 + (w ^ x4);
                const uint32_t hw = actH[idx], lw = actL[idx];
                float v0 = __uint_as_float(hw << 16) + __uint_as_float(lw << 16);
                float v1 = __uint_as_float(hw & 0xFFFF0000u) + __uint_as_float(lw & 0xFFFF0000u);
                s = fmaf(v0, __ldg(p.sigW + 2 * w), fmaf(v1, __ldg(p.sigW + 2 * w + 1), s));
            }
            sig = s;
        }
    }

    // rgb head on relu'd c-hidden (act) + output
    if (tid < 128) {
        const int m = tid, x4 = (m & 7) << 2;
        float r = 0.f, gq = 0.f, b = 0.f;
#pragma unroll 4
        for (int w = 0; w < 128; ++w) {
            const int idx = m * 128 + (w ^ x4);
            const uint32_t hw = actH[idx], lw = actL[idx];
            float v0 = __uint_as_float(hw << 16) + __uint_as_float(lw << 16);
            float v1 = __uint_as_float(hw & 0xFFFF0000u) + __uint_as_float(lw & 0xFFFF0000u);
            const float* c0 = p.c1W + (2 * w) * 3;
            r  = fmaf(v0, __ldg(c0 + 0), r);
            gq = fmaf(v0, __ldg(c0 + 1), gq);
            b  = fmaf(v0, __ldg(c0 + 2), b);
            r  = fmaf(v1, __ldg(c0 + 3), r);
            gq = fmaf(v1, __ldg(c0 + 4), gq);
            b  = fmaf(v1, __ldg(c0 + 5), b);
        }
        float4 o;
        o.x = r  + __ldg(p.c1b + 0);
        o.y = gq + __ldg(p.c1b + 1);
        o.z = b  + __ldg(p.c1b + 2);
        o.w = sig + __ldg(p.sigb);
        ((float4*)p.out)[blockIdx.x * 128 + m] = o;
    }
}

} // namespace

extern "C" void kernel_launch(void* const* d_in, const int* in_sizes, int n_in,
                              void* d_out, int out_size)
{
    KPW w;
    for (int i = 0; i < 5; ++i) w.W[i] = (const float*)d_in[2 + 2 * i];
    for (int i = 0; i < 3; ++i) w.W[5 + i] = (const float*)d_in[12 + 2 * i];
    w.W[8] = (const float*)d_in[18];

    KP p;
    p.x   = (const float*)d_in[0];
    p.dir = (const float*)d_in[1];
    for (int i = 0; i < 5; ++i) p.b[i] = (const float*)d_in[3 + 2 * i];
    for (int i = 0; i < 3; ++i) p.b[5 + i] = (const float*)d_in[13 + 2 * i];
    p.b[8] = (const float*)d_in[19];
    p.c1W  = (const float*)d_in[20]; p.c1b = (const float*)d_in[21];
    p.sigW = (const float*)d_in[22]; p.sigb = (const float*)d_in[23];
    p.out  = (float*)d_out;

    cudaFuncSetAttribute(nerf_mma, cudaFuncAttributeMaxDynamicSharedMemorySize, SMEM_BYTES);

    prep_kernel<<<NCHUNK, 256>>>(w);
    const int npts = in_sizes[0] / 3;
    nerf_mma<<<npts / 128, NTHREADS, SMEM_BYTES>>>(p);
}

// round 15
// speedup vs baseline: 1.5330x; 1.5330x over previous
#include <cuda_runtime.h>
#include <cuda_fp16.h>
#include <cstdint>

namespace {

constexpr int NCHUNK      = 35;
constexpr int CHUNK_BYTES = 65536;    // 64 k-rows: [hi 32KB][lo 32KB]; plane: 256 n-rows x 32 words
constexpr int NTHREADS    = 256;

// SMEM word offsets (uint32 units)
constexpr int W_ACT  = 0;         // 16384 words (128 rows x 128 words) fp16 act
constexpr int W_PE   = 16384;     // 4096 words (128 rows x 32 words) fp16 pe (shared x/dir)
constexpr int W_WBUF = 20480;     // 2 x 16384 words
constexpr int SMEM_BYTES = (20480 + 2 * 16384) * 4;   // 212992

__device__ __align__(128) unsigned char WPRE[(size_t)NCHUNK * CHUNK_BYTES];

__constant__ uint8_t CH_L[NCHUNK] = {
    0,
    1,1,1,1, 2,2,2,2, 3,3,3,3, 4,4,4,4,
    5,5,5,5,5, 6,6,6,6, 7,7,7,7, 8,8,8,8,8};
__constant__ uint16_t CH_K0[NCHUNK] = {
    0,
    0,64,128,192, 0,64,128,192, 0,64,128,192, 0,64,128,192,
    0,63,127,191,255, 0,64,128,192, 0,64,128,192, 0,39,103,167,231};
__constant__ uint8_t CH_KREAL[NCHUNK] = {
    63,
    64,64,64,64, 64,64,64,64, 64,64,64,64, 64,64,64,64,
    63,64,64,64,64, 64,64,64,64, 64,64,64,64, 39,64,64,64,64};
__constant__ int8_t NCKL[9]   = {1,4,4,4,4,5,4,4,5};
__constant__ int8_t RELU_L[9] = {1,1,1,1,0,1,1,0,1};

// ---------------- helpers ----------------
__device__ __forceinline__ uint32_t smem_u32(const void* p) {
    uint32_t a;
    asm("{ .reg .u64 t; cvta.to.shared.u64 t, %1; cvt.u32.u64 %0, t; }" : "=r"(a) : "l"(p));
    return a;
}
__device__ __forceinline__ void cp_async16(uint32_t s, const void* g) {
    asm volatile("cp.async.cg.shared.global [%0], [%1], 16;" :: "r"(s), "l"(g));
}
__device__ __forceinline__ void cp_commit() { asm volatile("cp.async.commit_group;" ::: "memory"); }
template <int n> __device__ __forceinline__ void cp_wait() {
    asm volatile("cp.async.wait_group %0;" :: "n"(n) : "memory");
}

__device__ __forceinline__ void mma16816(float* c, const uint32_t* a, const uint32_t* b) {
    asm volatile("mma.sync.aligned.m16n8k16.row.col.f32.f16.f16.f32 "
        "{%0,%1,%2,%3}, {%4,%5,%6,%7}, {%8,%9}, {%0,%1,%2,%3};"
        : "+f"(c[0]), "+f"(c[1]), "+f"(c[2]), "+f"(c[3])
        : "r"(a[0]), "r"(a[1]), "r"(a[2]), "r"(a[3]), "r"(b[0]), "r"(b[1]));
}

__device__ __forceinline__ uint32_t pack_h2(float a, float b) {
    __half2 h;
    h.x = __float2half_rn(a);
    h.y = __float2half_rn(b);
    return *reinterpret_cast<uint32_t*>(&h);
}
__device__ __forceinline__ void unpack_h2(uint32_t w, float& a, float& b) {
    __half2 h = *reinterpret_cast<__half2*>(&w);
    a = __low2float(h);
    b = __high2float(h);
}

// accurate sin/cos: double range reduction then fp32 sin/cos (matches fp32 ref)
__device__ __forceinline__ void sincos_red(float a, float& s, float& c) {
    double ad = (double)a;
    double k  = rint(ad * 0.15915494309189535);
    float rf  = (float)fma(k, -6.283185307179586, ad);
    s = sinf(rf); c = cosf(rf);
}

struct KPW { const float* W[9]; };
struct KP {
    const float* x; const float* dir;
    const float* b[9];
    const float* sigW; const float* sigb;
    const float* c1W;  const float* c1b;
    float* out;
};

// ---------------- weight prep: fp16 hi/lo split, transpose to [n][k], swizzle, pad ----------------
__global__ void prep_kernel(KPW pw) {
    const int gc = blockIdx.x;
    const int n  = threadIdx.x;
    const float* W  = pw.W[CH_L[gc]];
    const int k0    = CH_K0[gc];
    const int kreal = CH_KREAL[gc];
    unsigned char* dst = WPRE + (size_t)gc * CHUNK_BYTES;
    const int xn = (n & 7) << 2;
#pragma unroll
    for (int kk = 0; kk < 64; ++kk) {
        float v = (kk < kreal) ? W[(size_t)(k0 + kk) * 256 + n] : 0.f;
        __half h = __float2half_rn(v);
        __half l = __float2half_rn(v - __half2float(h));
        int word = (kk >> 1) ^ xn;
        int off  = n * 128 + word * 4 + (kk & 1) * 2;
        *(__half*)(dst + off)         = h;
        *(__half*)(dst + 32768 + off) = l;
    }
}

// ---------------- main kernel ----------------
__device__ __forceinline__ void load_chunk(uint32_t dstByte, int c, int tid) {
    const unsigned char* src = WPRE + (size_t)c * CHUNK_BYTES + tid * 16;
    uint32_t d = dstByte + tid * 16;
#pragma unroll
    for (int i = 0; i < 16; ++i)
        cp_async16(d + i * 4096, src + i * 4096);
    cp_commit();
}

__device__ __forceinline__ void put_pe(uint32_t* F, int m, int kk, float v) {
    int off = m * 32 + ((kk >> 1) ^ ((m & 7) << 2));
    ((__half*)(F + off))[kk & 1] = __float2half_rn(v);
}

// build PE plane (128 rows) for src (x: nlev=10, dir: nlev=6). Includes syncs.
__device__ void build_pe(uint32_t* F, const float* src, int nlev, int base, int tid) {
    for (int i = tid; i < 4096; i += NTHREADS) F[i] = 0;
    __syncthreads();
    for (int it = tid; it < 384; it += NTHREADS) {
        const int m = it & 127, comp = it >> 7;
        const float v = src[(base + m) * 3 + comp];
        put_pe(F, m, comp, v);
        float f = 1.f;
        for (int l = 0; l < nlev; ++l) {
            float s, c;
            sincos_red(v * f, s, c);
            put_pe(F, m, 3 + 6 * l + comp, s);
            put_pe(F, m, 3 + 6 * l + 3 + comp, c);
            f *= 2.f;
        }
    }
    __syncthreads();
}

__global__ __launch_bounds__(NTHREADS, 1) void nerf_mma(KP p) {
    extern __shared__ uint32_t sm4[];
    const int tid  = threadIdx.x;
    const int lane = tid & 31, warp = tid >> 5;
    const int g = lane >> 2, t = lane & 3;
    const int wm = warp & 1, wn = warp >> 1;   // warp grid 2(M) x 4(N), warp tile 64x64
    const int xg = g << 2;                     // swizzle xor (act/pe rows and W rows)

    uint32_t* actF = sm4 + W_ACT;
    uint32_t* peF  = sm4 + W_PE;
    const uint32_t wbufByte = smem_u32(sm4) + W_WBUF * 4;

    // kick off weight prefetch immediately, overlap with PE build
    load_chunk(wbufByte, 0, tid);
    load_chunk(wbufByte + CHUNK_BYTES, 1, tid);

    build_pe(peF, p.x, 10, blockIdx.x * 128, tid);

    float acc[4][8][4];
    float sig = 0.f;
    int gc = 0;

    for (int L = 0; L < 9; ++L) {
        // init accumulators with bias (uniform __ldg, L1-broadcast)
#pragma unroll
        for (int j = 0; j < 8; ++j) {
            const int n0 = wn * 64 + j * 8 + t * 2;
            const float b0 = __ldg(p.b[L] + n0), b1 = __ldg(p.b[L] + n0 + 1);
#pragma unroll
            for (int i2 = 0; i2 < 4; ++i2) {
                acc[i2][j][0] = b0; acc[i2][j][1] = b1;
                acc[i2][j][2] = b0; acc[i2][j][3] = b1;
            }
        }

        const int nck = NCKL[L];
        const bool concat = (L == 5 || L == 8);
        for (int ck = 0; ck < nck; ++ck) {
            if (gc < NCHUNK - 1) cp_wait<1>(); else cp_wait<0>();
            __syncthreads();
            const uint32_t* Wh  = sm4 + W_WBUF + (gc & 1) * 16384;
            const uint32_t* Wl  = Wh + 8192;
            const uint32_t* Whg = Wh + (wn * 64 + g) * 32;
            const uint32_t* Wlg = Wl + (wn * 64 + g) * 32;

            const bool pe = (L == 0) || (concat && ck == 0);
            const int ackBase = concat ? (ck - 1) * 4 : ck * 4;

#pragma unroll
            for (int s = 0; s < 4; ++s) {
                const int b0i = (s * 8 + t) ^ xg;
                const int b1i = (s * 8 + t + 4) ^ xg;
                uint32_t bh[8][2], bl[8][2];
#pragma unroll
                for (int j = 0; j < 8; ++j) {
                    bh[j][0] = Whg[j * 256 + b0i]; bh[j][1] = Whg[j * 256 + b1i];
                    bl[j][0] = Wlg[j * 256 + b0i]; bl[j][1] = Wlg[j * 256 + b1i];
                }

                const uint32_t* sA; int stride, kw;
                if (pe) { sA = peF;  stride = 32;  kw = s * 8; }
                else    { sA = actF; stride = 128; kw = (ackBase + s) * 8; }
                const int w0s = (kw + t) ^ xg, w1s = (kw + t + 4) ^ xg;

#pragma unroll
                for (int i2 = 0; i2 < 4; ++i2) {
                    const int r0 = wm * 64 + i2 * 16 + g;
                    const uint32_t* hA = sA + r0 * stride;
                    uint32_t ah[4];
                    ah[0] = hA[w0s]; ah[1] = hA[8 * stride + w0s];
                    ah[2] = hA[w1s]; ah[3] = hA[8 * stride + w1s];
#pragma unroll
                    for (int j = 0; j < 8; ++j) {
                        mma16816(acc[i2][j], ah, bh[j]);
                        mma16816(acc[i2][j], ah, bl[j]);
                    }
                }
            }
            __syncthreads();
            if (gc + 2 < NCHUNK) load_chunk(wbufByte + (gc & 1) * CHUNK_BYTES, gc + 2, tid);
            ++gc;
        }

        // epilogue: relu, fp16 pack, in-place act store
        const bool rl = RELU_L[L];
#pragma unroll
        for (int i2 = 0; i2 < 4; ++i2) {
            const int r0 = wm * 64 + i2 * 16 + g;
#pragma unroll
            for (int j = 0; j < 8; ++j) {
                const int cw  = wn * 32 + j * 4 + t;
                const int sw_ = cw ^ xg;
                float v0 = acc[i2][j][0], v1 = acc[i2][j][1];
                float v2 = acc[i2][j][2], v3 = acc[i2][j][3];
                if (rl) { v0 = fmaxf(v0,0.f); v1 = fmaxf(v1,0.f); v2 = fmaxf(v2,0.f); v3 = fmaxf(v3,0.f); }
                actF[r0 * 128 + sw_]       = pack_h2(v0, v1);
                actF[(r0 + 8) * 128 + sw_] = pack_h2(v2, v3);
            }
        }
        __syncthreads();

        if (L == 5) {   // pe_x dead; rebuild plane with pe_d for L8
            build_pe(peF, p.dir, 6, blockIdx.x * 128, tid);
        }

        if (L == 7 && tid < 128) {   // sigma head on features2 (raw), kept in register
            const int m = tid, x4 = (m & 7) << 2;
            float s = 0.f;
#pragma unroll 4
            for (int w = 0; w < 128; ++w) {
                float v0, v1;
                unpack_h2(actF[m * 128 + (w ^ x4)], v0, v1);
                s = fmaf(v0, __ldg(p.sigW + 2 * w), fmaf(v1, __ldg(p.sigW + 2 * w + 1), s));
            }
            sig = s;
        }
    }

    // rgb head on relu'd c-hidden (act) + output
    if (tid < 128) {
        const int m = tid, x4 = (m & 7) << 2;
        float r = 0.f, gq = 0.f, b = 0.f;
#pragma unroll 4
        for (int w = 0; w < 128; ++w) {
            float v0, v1;
            unpack_h2(actF[m * 128 + (w ^ x4)], v0, v1);
            const float* c0 = p.c1W + (2 * w) * 3;
            r  = fmaf(v0, __ldg(c0 + 0), r);
            gq = fmaf(v0, __ldg(c0 + 1), gq);
            b  = fmaf(v0, __ldg(c0 + 2), b);
            r  = fmaf(v1, __ldg(c0 + 3), r);
            gq = fmaf(v1, __ldg(c0 + 4), gq);
            b  = fmaf(v1, __ldg(c0 + 5), b);
        }
        float4 o;
        o.x = r  + __ldg(p.c1b + 0);
        o.y = gq + __ldg(p.c1b + 1);
        o.z = b  + __ldg(p.c1b + 2);
        o.w = sig + __ldg(p.sigb);
        ((float4*)p.out)[blockIdx.x * 128 + m] = o;
    }
}

} // namespace

extern "C" void kernel_launch(void* const* d_in, const int* in_sizes, int n_in,
                              void* d_out, int out_size)
{
    KPW w;
    for (int i = 0; i < 5; ++i) w.W[i] = (const float*)d_in[2 + 2 * i];
    for (int i = 0; i < 3; ++i) w.W[5 + i] = (const float*)d_in[12 + 2 * i];
    w.W[8] = (const float*)d_in[18];

    KP p;
    p.x   = (const float*)d_in[0];
    p.dir = (const float*)d_in[1];
    for (int i = 0; i < 5; ++i) p.b[i] = (const float*)d_in[3 + 2 * i];
    for (int i = 0; i < 3; ++i) p.b[5 + i] = (const float*)d_in[13 + 2 * i];
    p.b[8] = (const float*)d_in[19];
    p.c1W  = (const float*)d_in[20]; p.c1b = (const float*)d_in[21];
    p.sigW = (const float*)d_in[22]; p.sigb = (const float*)d_in[23];
    p.out  = (float*)d_out;

    cudaFuncSetAttribute(nerf_mma, cudaFuncAttributeMaxDynamicSharedMemorySize, SMEM_BYTES);

    prep_kernel<<<NCHUNK, 256>>>(w);
    const int npts = in_sizes[0] / 3;
    nerf_mma<<<npts / 128, NTHREADS, SMEM_BYTES>>>(p);
}

// round 16
// speedup vs baseline: 1.5365x; 1.0023x over previous
#include <cuda_runtime.h>
#include <cuda_fp16.h>
#include <cstdint>

namespace {

constexpr int NCHUNK      = 35;
constexpr int CHUNK_BYTES = 65536;    // 64 k-rows: [hi 32KB][lo 32KB]; plane: 256 n-rows x 32 words
constexpr int NTHREADS    = 256;

// SMEM word offsets (uint32 units)
constexpr int W_ACT  = 0;         // 16384 words (128 rows x 128 words) fp16 act
constexpr int W_PE   = 16384;     // 4096 words (128 rows x 32 words) fp16 pe (shared x/dir)
constexpr int W_WBUF = 20480;     // 2 x 16384 words
constexpr int SMEM_BYTES = (20480 + 2 * 16384) * 4;   // 212992

__device__ __align__(128) unsigned char WPRE[(size_t)NCHUNK * CHUNK_BYTES];

__constant__ uint8_t CH_L[NCHUNK] = {
    0,
    1,1,1,1, 2,2,2,2, 3,3,3,3, 4,4,4,4,
    5,5,5,5,5, 6,6,6,6, 7,7,7,7, 8,8,8,8,8};
__constant__ uint16_t CH_K0[NCHUNK] = {
    0,
    0,64,128,192, 0,64,128,192, 0,64,128,192, 0,64,128,192,
    0,63,127,191,255, 0,64,128,192, 0,64,128,192, 0,39,103,167,231};
__constant__ uint8_t CH_KREAL[NCHUNK] = {
    63,
    64,64,64,64, 64,64,64,64, 64,64,64,64, 64,64,64,64,
    63,64,64,64,64, 64,64,64,64, 64,64,64,64, 39,64,64,64,64};
__constant__ int8_t NCKL[9]   = {1,4,4,4,4,5,4,4,5};
__constant__ int8_t RELU_L[9] = {1,1,1,1,0,1,1,0,1};

// ---------------- helpers ----------------
__device__ __forceinline__ uint32_t smem_u32(const void* p) {
    uint32_t a;
    asm("{ .reg .u64 t; cvta.to.shared.u64 t, %1; cvt.u32.u64 %0, t; }" : "=r"(a) : "l"(p));
    return a;
}
__device__ __forceinline__ void cp_async16(uint32_t s, const void* g) {
    asm volatile("cp.async.cg.shared.global [%0], [%1], 16;" :: "r"(s), "l"(g));
}
__device__ __forceinline__ void cp_commit() { asm volatile("cp.async.commit_group;" ::: "memory"); }
template <int n> __device__ __forceinline__ void cp_wait() {
    asm volatile("cp.async.wait_group %0;" :: "n"(n) : "memory");
}

__device__ __forceinline__ void mma16816(float* c, const uint32_t* a, const uint32_t* b) {
    asm volatile("mma.sync.aligned.m16n8k16.row.col.f32.f16.f16.f32 "
        "{%0,%1,%2,%3}, {%4,%5,%6,%7}, {%8,%9}, {%0,%1,%2,%3};"
        : "+f"(c[0]), "+f"(c[1]), "+f"(c[2]), "+f"(c[3])
        : "r"(a[0]), "r"(a[1]), "r"(a[2]), "r"(a[3]), "r"(b[0]), "r"(b[1]));
}

__device__ __forceinline__ uint32_t pack_h2(float a, float b) {
    __half2 h;
    h.x = __float2half_rn(a);
    h.y = __float2half_rn(b);
    return *reinterpret_cast<uint32_t*>(&h);
}
__device__ __forceinline__ void unpack_h2(uint32_t w, float& a, float& b) {
    __half2 h = *reinterpret_cast<__half2*>(&w);
    a = __low2float(h);
    b = __high2float(h);
}

// accurate sin/cos: double range reduction then fp32 sin/cos (matches fp32 ref)
__device__ __forceinline__ void sincos_red(float a, float& s, float& c) {
    double ad = (double)a;
    double k  = rint(ad * 0.15915494309189535);
    float rf  = (float)fma(k, -6.283185307179586, ad);
    s = sinf(rf); c = cosf(rf);
}

struct KPW { const float* W[9]; };
struct KP {
    const float* x; const float* dir;
    const float* b[9];
    const float* sigW; const float* sigb;
    const float* c1W;  const float* c1b;
    float* out;
};

// ---------------- weight prep: fp16 hi/lo split, transpose to [n][k], swizzle, pad ----------------
__global__ void prep_kernel(KPW pw) {
    const int gc = blockIdx.x;
    const int n  = threadIdx.x;
    const float* W  = pw.W[CH_L[gc]];
    const int k0    = CH_K0[gc];
    const int kreal = CH_KREAL[gc];
    unsigned char* dst = WPRE + (size_t)gc * CHUNK_BYTES;
    const int xn = (n & 7) << 2;
#pragma unroll
    for (int kk = 0; kk < 64; ++kk) {
        float v = (kk < kreal) ? W[(size_t)(k0 + kk) * 256 + n] : 0.f;
        __half h = __float2half_rn(v);
        __half l = __float2half_rn(v - __half2float(h));
        int word = (kk >> 1) ^ xn;
        int off  = n * 128 + word * 4 + (kk & 1) * 2;
        *(__half*)(dst + off)         = h;
        *(__half*)(dst + 32768 + off) = l;
    }
}

// ---------------- main kernel ----------------
__device__ __forceinline__ void load_chunk(uint32_t dstByte, int c, int tid) {
    const unsigned char* src = WPRE + (size_t)c * CHUNK_BYTES + tid * 16;
    uint32_t d = dstByte + tid * 16;
#pragma unroll
    for (int i = 0; i < 16; ++i)
        cp_async16(d + i * 4096, src + i * 4096);
    cp_commit();
}

__device__ __forceinline__ void put_pe(uint32_t* F, int m, int kk, float v) {
    int off = m * 32 + ((kk >> 1) ^ ((m & 7) << 2));
    ((__half*)(F + off))[kk & 1] = __float2half_rn(v);
}

// build PE plane (128 rows) for src (x: nlev=10, dir: nlev=6). Includes syncs.
__device__ void build_pe(uint32_t* F, const float* src, int nlev, int base, int tid) {
    for (int i = tid; i < 4096; i += NTHREADS) F[i] = 0;
    __syncthreads();
    for (int it = tid; it < 384; it += NTHREADS) {
        const int m = it & 127, comp = it >> 7;
        const float v = src[(base + m) * 3 + comp];
        put_pe(F, m, comp, v);
        float f = 1.f;
        for (int l = 0; l < nlev; ++l) {
            float s, c;
            sincos_red(v * f, s, c);
            put_pe(F, m, 3 + 6 * l + comp, s);
            put_pe(F, m, 3 + 6 * l + 3 + comp, c);
            f *= 2.f;
        }
    }
    __syncthreads();
}

__global__ __launch_bounds__(NTHREADS, 1) void nerf_mma(KP p) {
    extern __shared__ uint32_t sm4[];
    const int tid  = threadIdx.x;
    const int lane = tid & 31, warp = tid >> 5;
    const int g = lane >> 2, t = lane & 3;
    const int wm = warp & 1, wn = warp >> 1;   // warp grid 2(M) x 4(N), warp tile 64x64
    const int xg = g << 2;                     // swizzle xor (act/pe rows and W rows)

    uint32_t* actF = sm4 + W_ACT;
    uint32_t* peF  = sm4 + W_PE;
    const uint32_t wbufByte = smem_u32(sm4) + W_WBUF * 4;

    // kick off weight prefetch immediately, overlap with PE build
    load_chunk(wbufByte, 0, tid);
    load_chunk(wbufByte + CHUNK_BYTES, 1, tid);

    build_pe(peF, p.x, 10, blockIdx.x * 128, tid);

    float acc[4][8][4];
    float sig = 0.f;
    int gc = 0;

    for (int L = 0; L < 9; ++L) {
        // init accumulators with bias (uniform __ldg, L1-broadcast)
#pragma unroll
        for (int j = 0; j < 8; ++j) {
            const int n0 = wn * 64 + j * 8 + t * 2;
            const float b0 = __ldg(p.b[L] + n0), b1 = __ldg(p.b[L] + n0 + 1);
#pragma unroll
            for (int i2 = 0; i2 < 4; ++i2) {
                acc[i2][j][0] = b0; acc[i2][j][1] = b1;
                acc[i2][j][2] = b0; acc[i2][j][3] = b1;
            }
        }

        const int nck = NCKL[L];
        const bool concat = (L == 5 || L == 8);
        for (int ck = 0; ck < nck; ++ck) {
            if (gc < NCHUNK - 1) cp_wait<1>(); else cp_wait<0>();
            __syncthreads();
            const uint32_t* Wh  = sm4 + W_WBUF + (gc & 1) * 16384;
            const uint32_t* Wl  = Wh + 8192;
            const uint32_t* Whg = Wh + (wn * 64 + g) * 32;
            const uint32_t* Wlg = Wl + (wn * 64 + g) * 32;

            const bool pe = (L == 0) || (concat && ck == 0);
            const int ackBase = concat ? (ck - 1) * 4 : ck * 4;

#pragma unroll
            for (int s = 0; s < 4; ++s) {
                const int b0i = (s * 8 + t) ^ xg;
                const int b1i = (s * 8 + t + 4) ^ xg;

                // A fragments for all 4 m-subtiles first (16 regs live)
                const uint32_t* sA; int stride, kw;
                if (pe) { sA = peF;  stride = 32;  kw = s * 8; }
                else    { sA = actF; stride = 128; kw = (ackBase + s) * 8; }
                const int w0s = (kw + t) ^ xg, w1s = (kw + t + 4) ^ xg;
                uint32_t ah[4][4];
#pragma unroll
                for (int i2 = 0; i2 < 4; ++i2) {
                    const int r0 = wm * 64 + i2 * 16 + g;
                    const uint32_t* hA = sA + r0 * stride;
                    ah[i2][0] = hA[w0s]; ah[i2][1] = hA[8 * stride + w0s];
                    ah[i2][2] = hA[w1s]; ah[i2][3] = hA[8 * stride + w1s];
                }

                // B in two j-groups of 4: only 16 B regs live at a time
#pragma unroll
                for (int jg = 0; jg < 2; ++jg) {
                    uint32_t bh[4][2], bl[4][2];
#pragma unroll
                    for (int j = 0; j < 4; ++j) {
                        const int jj = jg * 4 + j;
                        bh[j][0] = Whg[jj * 256 + b0i]; bh[j][1] = Whg[jj * 256 + b1i];
                        bl[j][0] = Wlg[jj * 256 + b0i]; bl[j][1] = Wlg[jj * 256 + b1i];
                    }
#pragma unroll
                    for (int i2 = 0; i2 < 4; ++i2) {
#pragma unroll
                        for (int j = 0; j < 4; ++j) {
                            mma16816(acc[i2][jg * 4 + j], ah[i2], bh[j]);
                            mma16816(acc[i2][jg * 4 + j], ah[i2], bl[j]);
                        }
                    }
                }
            }
            __syncthreads();
            if (gc + 2 < NCHUNK) load_chunk(wbufByte + (gc & 1) * CHUNK_BYTES, gc + 2, tid);
            ++gc;
        }

        // epilogue: relu, fp16 pack, in-place act store
        const bool rl = RELU_L[L];
#pragma unroll
        for (int i2 = 0; i2 < 4; ++i2) {
            const int r0 = wm * 64 + i2 * 16 + g;
#pragma unroll
            for (int j = 0; j < 8; ++j) {
                const int cw  = wn * 32 + j * 4 + t;
                const int sw_ = cw ^ xg;
                float v0 = acc[i2][j][0], v1 = acc[i2][j][1];
                float v2 = acc[i2][j][2], v3 = acc[i2][j][3];
                if (rl) { v0 = fmaxf(v0,0.f); v1 = fmaxf(v1,0.f); v2 = fmaxf(v2,0.f); v3 = fmaxf(v3,0.f); }
                actF[r0 * 128 + sw_]       = pack_h2(v0, v1);
                actF[(r0 + 8) * 128 + sw_] = pack_h2(v2, v3);
            }
        }
        __syncthreads();

        if (L == 5) {   // pe_x dead; rebuild plane with pe_d for L8
            build_pe(peF, p.dir, 6, blockIdx.x * 128, tid);
        }

        if (L == 7 && tid < 128) {   // sigma head on features2 (raw), kept in register
            const int m = tid, x4 = (m & 7) << 2;
            float s = 0.f;
#pragma unroll 4
            for (int w = 0; w < 128; ++w) {
                float v0, v1;
                unpack_h2(actF[m * 128 + (w ^ x4)], v0, v1);
                s = fmaf(v0, __ldg(p.sigW + 2 * w), fmaf(v1, __ldg(p.sigW + 2 * w + 1), s));
            }
            sig = s;
        }
    }

    // rgb head on relu'd c-hidden (act) + output
    if (tid < 128) {
        const int m = tid, x4 = (m & 7) << 2;
        float r = 0.f, gq = 0.f, b = 0.f;
#pragma unroll 4
        for (int w = 0; w < 128; ++w) {
            float v0, v1;
            unpack_h2(actF[m * 128 + (w ^ x4)], v0, v1);
            const float* c0 = p.c1W + (2 * w) * 3;
            r  = fmaf(v0, __ldg(c0 + 0), r);
            gq = fmaf(v0, __ldg(c0 + 1), gq);
            b  = fmaf(v0, __ldg(c0 + 2), b);
            r  = fmaf(v1, __ldg(c0 + 3), r);
            gq = fmaf(v1, __ldg(c0 + 4), gq);
            b  = fmaf(v1, __ldg(c0 + 5), b);
        }
        float4 o;
        o.x = r  + __ldg(p.c1b + 0);
        o.y = gq + __ldg(p.c1b + 1);
        o.z = b  + __ldg(p.c1b + 2);
        o.w = sig + __ldg(p.sigb);
        ((float4*)p.out)[blockIdx.x * 128 + m] = o;
    }
}

} // namespace

extern "C" void kernel_launch(void* const* d_in, const int* in_sizes, int n_in,
                              void* d_out, int out_size)
{
    KPW w;
    for (int i = 0; i < 5; ++i) w.W[i] = (const float*)d_in[2 + 2 * i];
    for (int i = 0; i < 3; ++i) w.W[5 + i] = (const float*)d_in[12 + 2 * i];
    w.W[8] = (const float*)d_in[18];

    KP p;
    p.x   = (const float*)d_in[0];
    p.dir = (const float*)d_in[1];
    for (int i = 0; i < 5; ++i) p.b[i] = (const float*)d_in[3 + 2 * i];
    for (int i = 0; i < 3; ++i) p.b[5 + i] = (const float*)d_in[13 + 2 * i];
    p.b[8] = (const float*)d_in[19];
    p.c1W  = (const float*)d_in[20]; p.c1b = (const float*)d_in[21];
    p.sigW = (const float*)d_in[22]; p.sigb = (const float*)d_in[23];
    p.out  = (float*)d_out;

    cudaFuncSetAttribute(nerf_mma, cudaFuncAttributeMaxDynamicSharedMemorySize, SMEM_BYTES);

    prep_kernel<<<NCHUNK, 256>>>(w);
    const int npts = in_sizes[0] / 3;
    nerf_mma<<<npts / 128, NTHREADS, SMEM_BYTES>>>(p);
}